// round 12
// baseline (speedup 1.0000x reference)
#include <cuda_runtime.h>
#include <cuda_bf16.h>
#include <math.h>

// Problem constants
#define Bb     4
#define Tt     2048
#define DIMd   512
#define NHEAD  8
#define DHEAD  64
#define MLPD   2048
#define ADIM   256
#define NTOK   (Bb * Tt)
#define MODC   (6 * DIMd)
#define QKVC   (3 * DIMd)
#define NQT    (Tt / 128)          // 16 q-tiles

typedef __nv_bfloat16 bf16;

// ---------------------------------------------------------------------------
// Scratch (static device globals; allocation-free per harness rules)
// ---------------------------------------------------------------------------
__device__ __align__(256) float g_x1 [NTOK * DIMd];          // fp32 residual

__device__ __align__(256) bf16 g_mod_bf [(size_t)NTOK * MODC];
__device__ __align__(256) bf16 g_silu_bf[NTOK * ADIM];
__device__ __align__(256) bf16 g_h_bf   [NTOK * DIMd];
__device__ __align__(256) bf16 g_qkv_bf [(size_t)NTOK * QKVC];
__device__ __align__(256) bf16 g_attn_bf[NTOK * DIMd];
__device__ __align__(256) bf16 g_mlp_bf [(size_t)NTOK * MLPD];

__device__ __align__(256) bf16 g_Wqkv_bf[QKVC * DIMd];
__device__ __align__(256) bf16 g_Wout_bf[DIMd * DIMd];
__device__ __align__(256) bf16 g_W1_bf  [MLPD * DIMd];
__device__ __align__(256) bf16 g_W2_bf  [DIMd * MLPD];
__device__ __align__(256) bf16 g_Wmod_bf[MODC * ADIM];

// ---------------------------------------------------------------------------
// Helpers
// ---------------------------------------------------------------------------
__device__ __forceinline__ unsigned smem_u32(const void* p)
{
    return (unsigned)__cvta_generic_to_shared(p);
}
__device__ __forceinline__ unsigned pack_bf2(float a, float b)
{
    __nv_bfloat162 t = __floats2bfloat162_rn(a, b);
    return *(unsigned*)&t;
}
__device__ __forceinline__ float gelu_exact(float v)
{
    return 0.5f * v * (1.0f + erff(v * 0.70710678118654752f));
}
__device__ __forceinline__ float fast_exp(float x)
{
    float y = x * 1.44269504088896f;
    y = fminf(fmaxf(y, -60.0f), 60.0f);
    float t = y + 12582912.0f;
    float f = y - (t - 12582912.0f);
    int   n = __float_as_int(t) - 0x4B400000;
    float p = 1.33336499e-3f;
    p = fmaf(p, f, 9.61817249e-3f);
    p = fmaf(p, f, 5.55036863e-2f);
    p = fmaf(p, f, 2.40226507e-1f);
    p = fmaf(p, f, 6.93147182e-1f);
    p = fmaf(p, f, 1.0f);
    return p * __int_as_float((n + 127) << 23);
}

// ---------------------------------------------------------------------------
// Fused prologue: all 5 weight conversions + SiLU in ONE launch.
// ---------------------------------------------------------------------------
#define P_S0 (NTOK * ADIM / 4)
#define P_S1 (P_S0 + QKVC * DIMd / 4)
#define P_S2 (P_S1 + DIMd * DIMd / 4)
#define P_S3 (P_S2 + MLPD * DIMd / 4)
#define P_S4 (P_S3 + DIMd * MLPD / 4)
#define P_S5 (P_S4 + MODC * ADIM / 4)

__global__ void prep_kernel(
    const float* __restrict__ aemb, const float* __restrict__ Wqkv,
    const float* __restrict__ Wout, const float* __restrict__ W1,
    const float* __restrict__ W2,   const float* __restrict__ Wmod,
    bf16* __restrict__ silu_o, bf16* __restrict__ wqkv_o,
    bf16* __restrict__ wout_o, bf16* __restrict__ w1_o,
    bf16* __restrict__ w2_o,   bf16* __restrict__ wmod_o)
{
    int i = blockIdx.x * blockDim.x + threadIdx.x;
    const float* src; bf16* dst; int base; bool is_silu = false;
    if      (i < P_S0) { src = aemb; dst = silu_o; base = i;        is_silu = true; }
    else if (i < P_S1) { src = Wqkv; dst = wqkv_o; base = i - P_S0; }
    else if (i < P_S2) { src = Wout; dst = wout_o; base = i - P_S1; }
    else if (i < P_S3) { src = W1;   dst = w1_o;   base = i - P_S2; }
    else if (i < P_S4) { src = W2;   dst = w2_o;   base = i - P_S3; }
    else if (i < P_S5) { src = Wmod; dst = wmod_o; base = i - P_S4; }
    else return;
    float4 v = ((const float4*)src)[base];
    if (is_silu) {
        v.x = v.x / (1.0f + __expf(-v.x));
        v.y = v.y / (1.0f + __expf(-v.y));
        v.z = v.z / (1.0f + __expf(-v.z));
        v.w = v.w / (1.0f + __expf(-v.w));
    }
    uint2 o;
    o.x = pack_bf2(v.x, v.y);
    o.y = pack_bf2(v.z, v.w);
    ((uint2*)dst)[base] = o;
}

// ---------------------------------------------------------------------------
// Fused LayerNorm + AdaLN modulation -> bf16
// ---------------------------------------------------------------------------
__global__ void lnmod_kernel(const float* __restrict__ x,
                             const bf16* __restrict__ mod,
                             int shift_off, int scale_off,
                             bf16* __restrict__ out)
{
    int row = blockIdx.x;
    int t   = threadIdx.x;
    const float* xr = x + (size_t)row * DIMd;

    float v[4];
    float s1 = 0.f, s2 = 0.f;
#pragma unroll
    for (int j = 0; j < 4; j++) {
        float z = xr[t + j * 128];
        v[j] = z; s1 += z; s2 += z * z;
    }
#pragma unroll
    for (int off = 16; off; off >>= 1) {
        s1 += __shfl_xor_sync(0xffffffffu, s1, off);
        s2 += __shfl_xor_sync(0xffffffffu, s2, off);
    }
    __shared__ float r1[4], r2[4];
    int w = t >> 5;
    if ((t & 31) == 0) { r1[w] = s1; r2[w] = s2; }
    __syncthreads();
    s1 = r1[0] + r1[1] + r1[2] + r1[3];
    s2 = r2[0] + r2[1] + r2[2] + r2[3];

    float mu   = s1 * (1.0f / DIMd);
    float var  = s2 * (1.0f / DIMd) - mu * mu;
    float rstd = rsqrtf(var + 1e-5f);

    const bf16* mrow = mod + (size_t)row * MODC;
    bf16* orow = out + (size_t)row * DIMd;
#pragma unroll
    for (int j = 0; j < 4; j++) {
        int c = t + j * 128;
        float sc = __bfloat162float(mrow[scale_off + c]);
        float sh = __bfloat162float(mrow[shift_off + c]);
        orow[c] = __float2bfloat16((v[j] - mu) * rstd * (1.0f + sc) + sh);
    }
}

// ---------------------------------------------------------------------------
// PERSISTENT bf16 tensor-core GEMM: 128x128x64 tiles, 3-stage cp.async ring
// flattened ACROSS tile boundaries (slot = flat_chunk % 3) so the next
// tile's loads stream during the current tile's last MMAs + epilogue.
// Grid = min(296, ntiles); each CTA walks tiles with stride gridDim.x.
// EPI: 1 = GELU(acc+bias) bf16, 2 = res + gate*(acc+bias) fp32, 3 = acc(+bias) bf16
// ---------------------------------------------------------------------------
#define GBM 128
#define GBN 128
#define GBK 64
#define GSTR (GBK + 8)
#define STAGES 3
#define STAGE_ELEMS (2 * GBM * GSTR)
#define GEMM_SMEM (STAGES * STAGE_ELEMS * 2)   // 110592 B
#define GEMM_GRID_CAP 296

__device__ __forceinline__ void g2s_chunk(
    const bf16* __restrict__ A, const bf16* __restrict__ Bw,
    int K, int ntn, int tile, int kt, int slot,
    bf16* smemBuf, int lr, int lc)
{
    const int bx = tile % ntn, by = tile / ntn;
    const bf16* Ag = A  + (size_t)(by * GBM) * K;
    const bf16* Bg = Bw + (size_t)(bx * GBN) * K;
    bf16* As = smemBuf + slot * STAGE_ELEMS;
    bf16* Bs = As + GBM * GSTR;
    const int k0 = kt * GBK;
#pragma unroll
    for (int p = 0; p < 4; p++) {
        int row = lr + p * 32;
        unsigned sA = smem_u32(&As[row * GSTR + lc]);
        asm volatile("cp.async.cg.shared.global [%0], [%1], 16;\n"
                     :: "r"(sA), "l"(Ag + (size_t)row * K + k0 + lc));
        unsigned sB = smem_u32(&Bs[row * GSTR + lc]);
        asm volatile("cp.async.cg.shared.global [%0], [%1], 16;\n"
                     :: "r"(sB), "l"(Bg + (size_t)row * K + k0 + lc));
    }
    asm volatile("cp.async.commit_group;\n" ::: "memory");
}

__device__ __forceinline__ void load_frags(
    const bf16* As, const bf16* Bs, int ks, int wm, int wn, int lane,
    unsigned aF[4][4], unsigned bF[4][2])
{
    const int kk = ks * 16;
#pragma unroll
    for (int i = 0; i < 4; i++) {
        int row = wm * 64 + i * 16 + (lane & 15);
        int col = kk + (lane >> 4) * 8;
        unsigned addr = smem_u32(&As[row * GSTR + col]);
        asm volatile(
            "ldmatrix.sync.aligned.m8n8.x4.shared.b16 {%0,%1,%2,%3}, [%4];\n"
            : "=r"(aF[i][0]), "=r"(aF[i][1]), "=r"(aF[i][2]), "=r"(aF[i][3])
            : "r"(addr));
    }
#pragma unroll
    for (int j = 0; j < 2; j++) {
        int row = wn * 32 + j * 16 + (lane >> 4) * 8 + (lane & 7);
        int col = kk + ((lane >> 3) & 1) * 8;
        unsigned addr = smem_u32(&Bs[row * GSTR + col]);
        unsigned r0, r1, r2, r3;
        asm volatile(
            "ldmatrix.sync.aligned.m8n8.x4.shared.b16 {%0,%1,%2,%3}, [%4];\n"
            : "=r"(r0), "=r"(r1), "=r"(r2), "=r"(r3)
            : "r"(addr));
        bF[2 * j + 0][0] = r0; bF[2 * j + 0][1] = r1;
        bF[2 * j + 1][0] = r2; bF[2 * j + 1][1] = r3;
    }
}

template <int EPI>
__global__ void __launch_bounds__(256) mma_gemm(
    const bf16* __restrict__ A,
    const bf16* __restrict__ Bw,
    const float* __restrict__ bias,
    const float* __restrict__ res,
    const bf16* __restrict__ gate, int gate_off,
    void* __restrict__ Cout,
    int M, int N, int K)
{
    extern __shared__ bf16 smemBuf[];

    const int tid  = threadIdx.x;
    const int wid  = tid >> 5, lane = tid & 31;
    const int wm   = wid & 1;
    const int wn   = wid >> 1;
    const int lr = tid >> 3;
    const int lc = (tid & 7) * 8;

    const int ntn    = N / GBN;
    const int ntiles = (M / GBM) * ntn;
    const int KT     = K / GBK;
    const int G      = gridDim.x;

    // my tiles: blockIdx.x, +G, +2G, ...  flattened into KT chunks each
    const int nmy   = (ntiles - blockIdx.x + G - 1) / G;
    if (nmy <= 0) return;
    const int total = nmy * KT;

    float acc[4][4][4];
#pragma unroll
    for (int i = 0; i < 4; i++)
#pragma unroll
        for (int j = 0; j < 4; j++)
#pragma unroll
            for (int r = 0; r < 4; r++) acc[i][j][r] = 0.f;

#define TILE_OF(c)  (blockIdx.x + ((c) / KT) * G)
#define KT_OF(c)    ((c) % KT)

    g2s_chunk(A, Bw, K, ntn, TILE_OF(0), KT_OF(0), 0, smemBuf, lr, lc);
    if (total > 1)
        g2s_chunk(A, Bw, K, ntn, TILE_OF(1), KT_OF(1), 1, smemBuf, lr, lc);

    const int grp = lane >> 2;
    const int qd  = (lane & 3) * 2;

    for (int c = 0; c < total; c++) {
        if (c + 1 >= total)
            asm volatile("cp.async.wait_group 0;" ::: "memory");
        else
            asm volatile("cp.async.wait_group 1;" ::: "memory");
        __syncthreads();

        if (c + 2 < total)
            g2s_chunk(A, Bw, K, ntn, TILE_OF(c + 2), KT_OF(c + 2),
                      (c + 2) % STAGES, smemBuf, lr, lc);

        const bf16* As = smemBuf + (c % STAGES) * STAGE_ELEMS;
        const bf16* Bs = As + GBM * GSTR;

#pragma unroll
        for (int ks = 0; ks < 4; ks++) {
            unsigned aF[4][4], bF[4][2];
            load_frags(As, Bs, ks, wm, wn, lane, aF, bF);
#pragma unroll
            for (int i = 0; i < 4; i++)
#pragma unroll
                for (int j = 0; j < 4; j++) {
                    asm volatile(
                        "mma.sync.aligned.m16n8k16.row.col.f32.bf16.bf16.f32 "
                        "{%0,%1,%2,%3}, {%4,%5,%6,%7}, {%8,%9}, {%0,%1,%2,%3};\n"
                        : "+f"(acc[i][j][0]), "+f"(acc[i][j][1]),
                          "+f"(acc[i][j][2]), "+f"(acc[i][j][3])
                        : "r"(aF[i][0]), "r"(aF[i][1]),
                          "r"(aF[i][2]), "r"(aF[i][3]),
                          "r"(bF[j][0]), "r"(bF[j][1]));
                }
        }

        if (KT_OF(c) == KT - 1) {
            // Epilogue for the finished tile (regs + gmem only; overlaps the
            // in-flight cp.asyncs of the next tile's chunks).
            const int tile = TILE_OF(c);
            const int bx = tile % ntn, by = tile / ntn;
#pragma unroll
            for (int i = 0; i < 4; i++) {
#pragma unroll
                for (int half = 0; half < 2; half++) {
                    int m = by * GBM + wm * 64 + i * 16 + grp + half * 8;
                    size_t crow = (size_t)m * N;
                    size_t grow = (size_t)m * MODC + gate_off;
#pragma unroll
                    for (int j = 0; j < 4; j++) {
                        int n = bx * GBN + wn * 32 + j * 8 + qd;
                        float v0 = acc[i][j][half * 2 + 0];
                        float v1 = acc[i][j][half * 2 + 1];
                        if (bias) { v0 += bias[n]; v1 += bias[n + 1]; }
                        if (EPI == 1) { v0 = gelu_exact(v0); v1 = gelu_exact(v1); }
                        if (EPI == 1 || EPI == 3) {
                            bf16* C = (bf16*)Cout;
                            *(unsigned*)(C + crow + n) = pack_bf2(v0, v1);
                        } else if (EPI == 2) {
                            float* C = (float*)Cout;
                            float g0 = __bfloat162float(gate[grow + n]);
                            float g1 = __bfloat162float(gate[grow + n + 1]);
                            C[crow + n]     = res[crow + n]     + g0 * v0;
                            C[crow + n + 1] = res[crow + n + 1] + g1 * v1;
                        }
                    }
                }
            }
#pragma unroll
            for (int i = 0; i < 4; i++)
#pragma unroll
                for (int j = 0; j < 4; j++)
#pragma unroll
                    for (int r = 0; r < 4; r++) acc[i][j][r] = 0.f;
        }
    }
#undef TILE_OF
#undef KT_OF
}

// ---------------------------------------------------------------------------
// Tensor-core causal flash attention, diagonal-paired (unchanged from 442.9us)
// ---------------------------------------------------------------------------
#define ASTR 72
#define KVTILE (64 * ASTR)
#define ATTN_SMEM (3 * 2 * KVTILE * 2)    // 55296 B dynamic

__device__ __forceinline__ void attn_prefetch(
    const bf16* __restrict__ qkv, bf16* pool, int b, int h, int kt, int tid)
{
    bf16* Ks = pool + (kt % 3) * 2 * KVTILE;
    bf16* Vs = Ks + KVTILE;
    const int k0 = kt * 64;
#pragma unroll
    for (int it = 0; it < 4; it++) {
        int idx = tid + it * 128;
        int row = idx >> 3, c8 = (idx & 7) * 8;
        const bf16* src = qkv + (size_t)(b * Tt + k0 + row) * QKVC + h * 64 + c8;
        asm volatile("cp.async.cg.shared.global [%0], [%1], 16;\n"
                     :: "r"(smem_u32(&Ks[row * ASTR + c8])), "l"(src + 512));
        asm volatile("cp.async.cg.shared.global [%0], [%1], 16;\n"
                     :: "r"(smem_u32(&Vs[row * ASTR + c8])), "l"(src + 1024));
    }
    asm volatile("cp.async.commit_group;\n" ::: "memory");
}

__global__ void __launch_bounds__(128) attn_tc_kernel(
    const bf16* __restrict__ qkv, bf16* __restrict__ out)
{
    extern __shared__ bf16 pool[];
    const int b  = blockIdx.z, h = blockIdx.y, pair = blockIdx.x;
    const int tid = threadIdx.x, w = tid >> 5, lane = tid & 31;

#pragma unroll 1
    for (int hh = 0; hh < 2; hh++) {
        const int qt = hh ? (NQT - 1 - pair) : pair;

        __syncthreads();

#pragma unroll
        for (int it = 0; it < 8; it++) {
            int idx = tid + it * 128;
            int row = idx >> 3, c8 = (idx & 7) * 8;
            const bf16* src =
                qkv + (size_t)(b * Tt + qt * 128 + row) * QKVC + h * 64 + c8;
            asm volatile("cp.async.cg.shared.global [%0], [%1], 16;\n"
                         :: "r"(smem_u32(&pool[row * ASTR + c8])), "l"(src));
        }
        asm volatile("cp.async.commit_group;\n" ::: "memory");
        asm volatile("cp.async.wait_group 0;" ::: "memory");
        __syncthreads();

        unsigned qF[2][4][4];
#pragma unroll
        for (int i = 0; i < 2; i++)
#pragma unroll
            for (int kk = 0; kk < 4; kk++) {
                int row = w * 32 + i * 16 + (lane & 15);
                int col = kk * 16 + (lane >> 4) * 8;
                unsigned addr = smem_u32(&pool[row * ASTR + col]);
                asm volatile(
                    "ldmatrix.sync.aligned.m8n8.x4.shared.b16 {%0,%1,%2,%3}, [%4];\n"
                    : "=r"(qF[i][kk][0]), "=r"(qF[i][kk][1]),
                      "=r"(qF[i][kk][2]), "=r"(qF[i][kk][3])
                    : "r"(addr));
            }
        __syncthreads();

        float oAcc[2][8][4];
#pragma unroll
        for (int i = 0; i < 2; i++)
#pragma unroll
            for (int j = 0; j < 8; j++)
#pragma unroll
                for (int r = 0; r < 4; r++) oAcc[i][j][r] = 0.f;
        float lsum[2][2] = {{0.f, 0.f}, {0.f, 0.f}};

        const int qmax  = qt * 128 + w * 32 + 31;
        const int ntile = 2 * (qt + 1);

        attn_prefetch(qkv, pool, b, h, 0, tid);
        if (ntile > 1) attn_prefetch(qkv, pool, b, h, 1, tid);

        for (int kt = 0; kt < ntile; kt++) {
            if (kt + 1 >= ntile)
                asm volatile("cp.async.wait_group 0;" ::: "memory");
            else
                asm volatile("cp.async.wait_group 1;" ::: "memory");
            __syncthreads();

            if (kt + 2 < ntile) attn_prefetch(qkv, pool, b, h, kt + 2, tid);

            const bf16* Ks = pool + (kt % 3) * 2 * KVTILE;
            const bf16* Vs = Ks + KVTILE;
            const int k0 = kt * 64;

            if (k0 <= qmax) {
                float sAcc[2][8][4];
#pragma unroll
                for (int i = 0; i < 2; i++)
#pragma unroll
                    for (int j = 0; j < 8; j++)
#pragma unroll
                        for (int r = 0; r < 4; r++) sAcc[i][j][r] = 0.f;

#pragma unroll
                for (int kk = 0; kk < 4; kk++) {
#pragma unroll
                    for (int j2 = 0; j2 < 4; j2++) {
                        int row = j2 * 16 + (lane >> 4) * 8 + (lane & 7);
                        int col = kk * 16 + ((lane >> 3) & 1) * 8;
                        unsigned addr = smem_u32(&Ks[row * ASTR + col]);
                        unsigned r0, r1, r2, r3;
                        asm volatile(
                            "ldmatrix.sync.aligned.m8n8.x4.shared.b16 {%0,%1,%2,%3}, [%4];\n"
                            : "=r"(r0), "=r"(r1), "=r"(r2), "=r"(r3) : "r"(addr));
#pragma unroll
                        for (int i = 0; i < 2; i++) {
                            asm volatile(
                                "mma.sync.aligned.m16n8k16.row.col.f32.bf16.bf16.f32 "
                                "{%0,%1,%2,%3}, {%4,%5,%6,%7}, {%8,%9}, {%0,%1,%2,%3};\n"
                                : "+f"(sAcc[i][2*j2][0]), "+f"(sAcc[i][2*j2][1]),
                                  "+f"(sAcc[i][2*j2][2]), "+f"(sAcc[i][2*j2][3])
                                : "r"(qF[i][kk][0]), "r"(qF[i][kk][1]),
                                  "r"(qF[i][kk][2]), "r"(qF[i][kk][3]),
                                  "r"(r0), "r"(r1));
                            asm volatile(
                                "mma.sync.aligned.m16n8k16.row.col.f32.bf16.bf16.f32 "
                                "{%0,%1,%2,%3}, {%4,%5,%6,%7}, {%8,%9}, {%0,%1,%2,%3};\n"
                                : "+f"(sAcc[i][2*j2+1][0]), "+f"(sAcc[i][2*j2+1][1]),
                                  "+f"(sAcc[i][2*j2+1][2]), "+f"(sAcc[i][2*j2+1][3])
                                : "r"(qF[i][kk][0]), "r"(qF[i][kk][1]),
                                  "r"(qF[i][kk][2]), "r"(qF[i][kk][3]),
                                  "r"(r2), "r"(r3));
                        }
                    }
                }

                const int qrow0 = qt * 128 + w * 32 + (lane >> 2);
#pragma unroll
                for (int i = 0; i < 2; i++) {
                    int q0 = qrow0 + i * 16;
                    int q1 = q0 + 8;
#pragma unroll
                    for (int j = 0; j < 8; j++) {
                        int kc = k0 + j * 8 + (lane & 3) * 2;
                        float p0 = (kc     <= q0) ? fast_exp(sAcc[i][j][0] * 0.125f) : 0.f;
                        float p1 = (kc + 1 <= q0) ? fast_exp(sAcc[i][j][1] * 0.125f) : 0.f;
                        float p2 = (kc     <= q1) ? fast_exp(sAcc[i][j][2] * 0.125f) : 0.f;
                        float p3 = (kc + 1 <= q1) ? fast_exp(sAcc[i][j][3] * 0.125f) : 0.f;
                        sAcc[i][j][0] = p0; sAcc[i][j][1] = p1;
                        sAcc[i][j][2] = p2; sAcc[i][j][3] = p3;
                        lsum[i][0] += p0 + p1;
                        lsum[i][1] += p2 + p3;
                    }
                }

#pragma unroll
                for (int c = 0; c < 4; c++) {
                    unsigned pF[2][4];
#pragma unroll
                    for (int i = 0; i < 2; i++) {
                        pF[i][0] = pack_bf2(sAcc[i][2*c  ][0], sAcc[i][2*c  ][1]);
                        pF[i][1] = pack_bf2(sAcc[i][2*c  ][2], sAcc[i][2*c  ][3]);
                        pF[i][2] = pack_bf2(sAcc[i][2*c+1][0], sAcc[i][2*c+1][1]);
                        pF[i][3] = pack_bf2(sAcc[i][2*c+1][2], sAcc[i][2*c+1][3]);
                    }
#pragma unroll
                    for (int d2 = 0; d2 < 4; d2++) {
                        int g = lane >> 3;
                        int row = c * 16 + (g & 1) * 8 + (lane & 7);
                        int col = d2 * 16 + (g >> 1) * 8;
                        unsigned addr = smem_u32(&Vs[row * ASTR + col]);
                        unsigned v0, v1, v2, v3;
                        asm volatile(
                            "ldmatrix.sync.aligned.m8n8.x4.trans.shared.b16 {%0,%1,%2,%3}, [%4];\n"
                            : "=r"(v0), "=r"(v1), "=r"(v2), "=r"(v3) : "r"(addr));
#pragma unroll
                        for (int i = 0; i < 2; i++) {
                            asm volatile(
                                "mma.sync.aligned.m16n8k16.row.col.f32.bf16.bf16.f32 "
                                "{%0,%1,%2,%3}, {%4,%5,%6,%7}, {%8,%9}, {%0,%1,%2,%3};\n"
                                : "+f"(oAcc[i][2*d2][0]), "+f"(oAcc[i][2*d2][1]),
                                  "+f"(oAcc[i][2*d2][2]), "+f"(oAcc[i][2*d2][3])
                                : "r"(pF[i][0]), "r"(pF[i][1]), "r"(pF[i][2]), "r"(pF[i][3]),
                                  "r"(v0), "r"(v1));
                            asm volatile(
                                "mma.sync.aligned.m16n8k16.row.col.f32.bf16.bf16.f32 "
                                "{%0,%1,%2,%3}, {%4,%5,%6,%7}, {%8,%9}, {%0,%1,%2,%3};\n"
                                : "+f"(oAcc[i][2*d2+1][0]), "+f"(oAcc[i][2*d2+1][1]),
                                  "+f"(oAcc[i][2*d2+1][2]), "+f"(oAcc[i][2*d2+1][3])
                                : "r"(pF[i][0]), "r"(pF[i][1]), "r"(pF[i][2]), "r"(pF[i][3]),
                                  "r"(v2), "r"(v3));
                        }
                    }
                }
            }
        }

#pragma unroll
        for (int i = 0; i < 2; i++) {
#pragma unroll
            for (int hf = 0; hf < 2; hf++) {
                float l = lsum[i][hf];
                l += __shfl_xor_sync(0xffffffffu, l, 1);
                l += __shfl_xor_sync(0xffffffffu, l, 2);
                float inv = 1.0f / l;
                int qg = qt * 128 + w * 32 + i * 16 + (lane >> 2) + hf * 8;
                bf16* orow = out + (size_t)(b * Tt + qg) * DIMd + h * DHEAD;
#pragma unroll
                for (int j = 0; j < 8; j++) {
                    int d = j * 8 + (lane & 3) * 2;
                    *(unsigned*)(orow + d) =
                        pack_bf2(oAcc[i][j][hf * 2] * inv, oAcc[i][j][hf * 2 + 1] * inv);
                }
            }
        }
    }
}

// ---------------------------------------------------------------------------
// Launch
// Inputs: 0:x 1:action_emb 2:causal_mask 3:Wqkv 4:Wout 5:bout
//         6:W1 7:b1 8:W2 9:b2 10:Wmod 11:bmod
// ---------------------------------------------------------------------------
static inline int gemm_grid(int M, int N)
{
    int t = (M / GBM) * (N / GBN);
    return t < GEMM_GRID_CAP ? t : GEMM_GRID_CAP;
}

extern "C" void kernel_launch(void* const* d_in, const int* in_sizes, int n_in,
                              void* d_out, int out_size)
{
    const float* x    = (const float*)d_in[0];
    const float* aemb = (const float*)d_in[1];
    const float* Wqkv = (const float*)d_in[3];
    const float* Wout = (const float*)d_in[4];
    const float* bout = (const float*)d_in[5];
    const float* W1   = (const float*)d_in[6];
    const float* b1   = (const float*)d_in[7];
    const float* W2   = (const float*)d_in[8];
    const float* b2   = (const float*)d_in[9];
    const float* Wmod = (const float*)d_in[10];
    const float* bmod = (const float*)d_in[11];
    float* out = (float*)d_out;

    float *x1_p;
    bf16 *mod_p, *silu_p, *h_p, *qkv_p, *attn_p, *mlp_p;
    bf16 *wqkv_p, *wout_p, *w1_p, *w2_p, *wmod_p;
    cudaGetSymbolAddress((void**)&x1_p,   g_x1);
    cudaGetSymbolAddress((void**)&mod_p,  g_mod_bf);
    cudaGetSymbolAddress((void**)&silu_p, g_silu_bf);
    cudaGetSymbolAddress((void**)&h_p,    g_h_bf);
    cudaGetSymbolAddress((void**)&qkv_p,  g_qkv_bf);
    cudaGetSymbolAddress((void**)&attn_p, g_attn_bf);
    cudaGetSymbolAddress((void**)&mlp_p,  g_mlp_bf);
    cudaGetSymbolAddress((void**)&wqkv_p, g_Wqkv_bf);
    cudaGetSymbolAddress((void**)&wout_p, g_Wout_bf);
    cudaGetSymbolAddress((void**)&w1_p,   g_W1_bf);
    cudaGetSymbolAddress((void**)&w2_p,   g_W2_bf);
    cudaGetSymbolAddress((void**)&wmod_p, g_Wmod_bf);

    cudaFuncSetAttribute(mma_gemm<1>, cudaFuncAttributeMaxDynamicSharedMemorySize, GEMM_SMEM);
    cudaFuncSetAttribute(mma_gemm<2>, cudaFuncAttributeMaxDynamicSharedMemorySize, GEMM_SMEM);
    cudaFuncSetAttribute(mma_gemm<3>, cudaFuncAttributeMaxDynamicSharedMemorySize, GEMM_SMEM);
    cudaFuncSetAttribute(attn_tc_kernel, cudaFuncAttributeMaxDynamicSharedMemorySize, ATTN_SMEM);

    // 1) fused prologue
    prep_kernel<<<(P_S5 + 255) / 256, 256>>>(
        aemb, Wqkv, Wout, W1, W2, Wmod,
        silu_p, wqkv_p, wout_p, w1_p, w2_p, wmod_p);

    // 2) mod = silu_a @ Wmod^T + bmod -> bf16
    mma_gemm<3><<<gemm_grid(NTOK, MODC), 256, GEMM_SMEM>>>(
        silu_p, wmod_p, bmod, nullptr, nullptr, 0, mod_p, NTOK, MODC, ADIM);

    // 3) h = LN(x)*(1+scale1)+shift1 -> bf16
    lnmod_kernel<<<NTOK, 128>>>(x, mod_p, 0, DIMd, h_p);

    // 4) qkv = h @ Wqkv^T -> bf16
    mma_gemm<3><<<gemm_grid(NTOK, QKVC), 256, GEMM_SMEM>>>(
        h_p, wqkv_p, nullptr, nullptr, nullptr, 0, qkv_p, NTOK, QKVC, DIMd);

    // 5) tensor-core causal attention (diagonal-paired) -> bf16
    attn_tc_kernel<<<dim3(NQT / 2, NHEAD, Bb), 128, ATTN_SMEM>>>(qkv_p, attn_p);

    // 6) x1 = x + gate1 * (attn @ Wout^T + bout)  fp32 out
    mma_gemm<2><<<gemm_grid(NTOK, DIMd), 256, GEMM_SMEM>>>(
        attn_p, wout_p, bout, x, mod_p, 2 * DIMd, x1_p, NTOK, DIMd, DIMd);

    // 7) h = LN(x1)*(1+scale2)+shift2 -> bf16
    lnmod_kernel<<<NTOK, 128>>>(x1_p, mod_p, 3 * DIMd, 4 * DIMd, h_p);

    // 8) mlp = gelu(h @ W1^T + b1) -> bf16
    mma_gemm<1><<<gemm_grid(NTOK, MLPD), 256, GEMM_SMEM>>>(
        h_p, w1_p, b1, nullptr, nullptr, 0, mlp_p, NTOK, MLPD, DIMd);

    // 9) out = x1 + gate2 * (mlp @ W2^T + b2)  fp32 out
    mma_gemm<2><<<gemm_grid(NTOK, DIMd), 256, GEMM_SMEM>>>(
        mlp_p, w2_p, b2, x1_p, mod_p, 5 * DIMd, out, NTOK, DIMd, MLPD);
}

// round 13
// speedup vs baseline: 1.0724x; 1.0724x over previous
#include <cuda_runtime.h>
#include <cuda_bf16.h>
#include <math.h>

// Problem constants
#define Bb     4
#define Tt     2048
#define DIMd   512
#define NHEAD  8
#define DHEAD  64
#define MLPD   2048
#define ADIM   256
#define NTOK   (Bb * Tt)
#define MODC   (6 * DIMd)
#define QKVC   (3 * DIMd)
#define NQT    (Tt / 128)          // 16 q-tiles

typedef __nv_bfloat16 bf16;

// ---------------------------------------------------------------------------
// Scratch (static device globals; allocation-free per harness rules)
// ---------------------------------------------------------------------------
__device__ __align__(256) float g_x1 [NTOK * DIMd];          // fp32 residual

__device__ __align__(256) bf16 g_mod_bf [(size_t)NTOK * MODC];
__device__ __align__(256) bf16 g_silu_bf[NTOK * ADIM];
__device__ __align__(256) bf16 g_h_bf   [NTOK * DIMd];
__device__ __align__(256) bf16 g_qkv_bf [(size_t)NTOK * QKVC];
__device__ __align__(256) bf16 g_attn_bf[NTOK * DIMd];
__device__ __align__(256) bf16 g_mlp_bf [(size_t)NTOK * MLPD];

__device__ __align__(256) bf16 g_Wqkv_bf[QKVC * DIMd];
__device__ __align__(256) bf16 g_Wout_bf[DIMd * DIMd];
__device__ __align__(256) bf16 g_W1_bf  [MLPD * DIMd];
__device__ __align__(256) bf16 g_W2_bf  [DIMd * MLPD];
__device__ __align__(256) bf16 g_Wmod_bf[MODC * ADIM];

// ---------------------------------------------------------------------------
// Helpers
// ---------------------------------------------------------------------------
__device__ __forceinline__ unsigned smem_u32(const void* p)
{
    return (unsigned)__cvta_generic_to_shared(p);
}
__device__ __forceinline__ unsigned pack_bf2(float a, float b)
{
    __nv_bfloat162 t = __floats2bfloat162_rn(a, b);
    return *(unsigned*)&t;
}
__device__ __forceinline__ float gelu_exact(float v)
{
    return 0.5f * v * (1.0f + erff(v * 0.70710678118654752f));
}
__device__ __forceinline__ float fast_exp(float x)
{
    float y = x * 1.44269504088896f;
    y = fminf(fmaxf(y, -60.0f), 60.0f);
    float t = y + 12582912.0f;
    float f = y - (t - 12582912.0f);
    int   n = __float_as_int(t) - 0x4B400000;
    float p = 1.33336499e-3f;
    p = fmaf(p, f, 9.61817249e-3f);
    p = fmaf(p, f, 5.55036863e-2f);
    p = fmaf(p, f, 2.40226507e-1f);
    p = fmaf(p, f, 6.93147182e-1f);
    p = fmaf(p, f, 1.0f);
    return p * __int_as_float((n + 127) << 23);
}

// ---------------------------------------------------------------------------
// Fused prologue: all 5 weight conversions + SiLU in ONE launch.
// ---------------------------------------------------------------------------
#define P_S0 (NTOK * ADIM / 4)
#define P_S1 (P_S0 + QKVC * DIMd / 4)
#define P_S2 (P_S1 + DIMd * DIMd / 4)
#define P_S3 (P_S2 + MLPD * DIMd / 4)
#define P_S4 (P_S3 + DIMd * MLPD / 4)
#define P_S5 (P_S4 + MODC * ADIM / 4)

__global__ void prep_kernel(
    const float* __restrict__ aemb, const float* __restrict__ Wqkv,
    const float* __restrict__ Wout, const float* __restrict__ W1,
    const float* __restrict__ W2,   const float* __restrict__ Wmod,
    bf16* __restrict__ silu_o, bf16* __restrict__ wqkv_o,
    bf16* __restrict__ wout_o, bf16* __restrict__ w1_o,
    bf16* __restrict__ w2_o,   bf16* __restrict__ wmod_o)
{
    int i = blockIdx.x * blockDim.x + threadIdx.x;
    const float* src; bf16* dst; int base; bool is_silu = false;
    if      (i < P_S0) { src = aemb; dst = silu_o; base = i;        is_silu = true; }
    else if (i < P_S1) { src = Wqkv; dst = wqkv_o; base = i - P_S0; }
    else if (i < P_S2) { src = Wout; dst = wout_o; base = i - P_S1; }
    else if (i < P_S3) { src = W1;   dst = w1_o;   base = i - P_S2; }
    else if (i < P_S4) { src = W2;   dst = w2_o;   base = i - P_S3; }
    else if (i < P_S5) { src = Wmod; dst = wmod_o; base = i - P_S4; }
    else return;
    float4 v = ((const float4*)src)[base];
    if (is_silu) {
        v.x = v.x / (1.0f + __expf(-v.x));
        v.y = v.y / (1.0f + __expf(-v.y));
        v.z = v.z / (1.0f + __expf(-v.z));
        v.w = v.w / (1.0f + __expf(-v.w));
    }
    uint2 o;
    o.x = pack_bf2(v.x, v.y);
    o.y = pack_bf2(v.z, v.w);
    ((uint2*)dst)[base] = o;
}

// ---------------------------------------------------------------------------
// Fused LayerNorm + AdaLN modulation -> bf16
// ---------------------------------------------------------------------------
__global__ void lnmod_kernel(const float* __restrict__ x,
                             const bf16* __restrict__ mod,
                             int shift_off, int scale_off,
                             bf16* __restrict__ out)
{
    int row = blockIdx.x;
    int t   = threadIdx.x;
    const float* xr = x + (size_t)row * DIMd;

    float v[4];
    float s1 = 0.f, s2 = 0.f;
#pragma unroll
    for (int j = 0; j < 4; j++) {
        float z = xr[t + j * 128];
        v[j] = z; s1 += z; s2 += z * z;
    }
#pragma unroll
    for (int off = 16; off; off >>= 1) {
        s1 += __shfl_xor_sync(0xffffffffu, s1, off);
        s2 += __shfl_xor_sync(0xffffffffu, s2, off);
    }
    __shared__ float r1[4], r2[4];
    int w = t >> 5;
    if ((t & 31) == 0) { r1[w] = s1; r2[w] = s2; }
    __syncthreads();
    s1 = r1[0] + r1[1] + r1[2] + r1[3];
    s2 = r2[0] + r2[1] + r2[2] + r2[3];

    float mu   = s1 * (1.0f / DIMd);
    float var  = s2 * (1.0f / DIMd) - mu * mu;
    float rstd = rsqrtf(var + 1e-5f);

    const bf16* mrow = mod + (size_t)row * MODC;
    bf16* orow = out + (size_t)row * DIMd;
#pragma unroll
    for (int j = 0; j < 4; j++) {
        int c = t + j * 128;
        float sc = __bfloat162float(mrow[scale_off + c]);
        float sh = __bfloat162float(mrow[shift_off + c]);
        orow[c] = __float2bfloat16((v[j] - mu) * rstd * (1.0f + sc) + sh);
    }
}

// ---------------------------------------------------------------------------
// bf16 tensor-core GEMM: 128x128x64 tiles, 3-stage cp.async pipeline,
// one __syncthreads per 64-K tile. ldmatrix addresses PRECOMPUTED outside
// the mainloop (base + stage offset + ks*32B) to strip per-ks ALU.
// EPI: 1 = GELU(acc+bias) bf16, 2 = res + gate*(acc+bias) fp32, 3 = acc(+bias) bf16
// ---------------------------------------------------------------------------
#define GBM 128
#define GBN 128
#define GBK 64
#define GSTR (GBK + 8)
#define STAGES 3
#define STAGE_ELEMS (2 * GBM * GSTR)
#define STAGE_BYTES (STAGE_ELEMS * 2)
#define GEMM_SMEM (STAGES * STAGE_BYTES)       // 110592 B

__device__ __forceinline__ void g2s_tile(
    const bf16* __restrict__ Ag, const bf16* __restrict__ Bg,
    int K, int kt, bf16* smemBuf, int lr, int lc)
{
    bf16* As = smemBuf + (kt % STAGES) * STAGE_ELEMS;
    bf16* Bs = As + GBM * GSTR;
    const int k0 = kt * GBK;
#pragma unroll
    for (int p = 0; p < 4; p++) {
        int row = lr + p * 32;
        unsigned sA = smem_u32(&As[row * GSTR + lc]);
        asm volatile("cp.async.cg.shared.global [%0], [%1], 16;\n"
                     :: "r"(sA), "l"(Ag + (size_t)row * K + k0 + lc));
        unsigned sB = smem_u32(&Bs[row * GSTR + lc]);
        asm volatile("cp.async.cg.shared.global [%0], [%1], 16;\n"
                     :: "r"(sB), "l"(Bg + (size_t)row * K + k0 + lc));
    }
    asm volatile("cp.async.commit_group;\n" ::: "memory");
}

template <int EPI>
__global__ void __launch_bounds__(256) mma_gemm(
    const bf16* __restrict__ A,
    const bf16* __restrict__ Bw,
    const float* __restrict__ bias,
    const float* __restrict__ res,
    const bf16* __restrict__ gate, int gate_off,
    void* __restrict__ Cout,
    int M, int N, int K)
{
    extern __shared__ bf16 smemBuf[];

    const int tid  = threadIdx.x;
    const int bx   = blockIdx.x, by = blockIdx.y;
    const int wid  = tid >> 5, lane = tid & 31;
    const int wm   = wid & 1;
    const int wn   = wid >> 1;

    const int lr = tid >> 3;
    const int lc = (tid & 7) * 8;
    const bf16* Ag = A  + (size_t)(by * GBM) * K;
    const bf16* Bg = Bw + (size_t)(bx * GBN) * K;

    // Precomputed ldmatrix base addresses (stage 0, ks 0), bytes.
    unsigned aBase[4], bBase[2];
#pragma unroll
    for (int i = 0; i < 4; i++) {
        int row = wm * 64 + i * 16 + (lane & 15);
        int col = (lane >> 4) * 8;
        aBase[i] = smem_u32(&smemBuf[row * GSTR + col]);
    }
#pragma unroll
    for (int j = 0; j < 2; j++) {
        int row = wn * 32 + j * 16 + (lane >> 4) * 8 + (lane & 7);
        int col = ((lane >> 3) & 1) * 8;
        bBase[j] = smem_u32(&smemBuf[GBM * GSTR + row * GSTR + col]);
    }

    float acc[4][4][4];
#pragma unroll
    for (int i = 0; i < 4; i++)
#pragma unroll
        for (int j = 0; j < 4; j++)
#pragma unroll
            for (int r = 0; r < 4; r++) acc[i][j][r] = 0.f;

    const int KT = K / GBK;

    g2s_tile(Ag, Bg, K, 0, smemBuf, lr, lc);
    g2s_tile(Ag, Bg, K, 1, smemBuf, lr, lc);

    unsigned soff = 0;
    for (int kt = 0; kt < KT; kt++) {
        if (kt + 1 >= KT)
            asm volatile("cp.async.wait_group 0;" ::: "memory");
        else
            asm volatile("cp.async.wait_group 1;" ::: "memory");
        __syncthreads();

        if (kt + 2 < KT) g2s_tile(Ag, Bg, K, kt + 2, smemBuf, lr, lc);

#pragma unroll
        for (int ks = 0; ks < 4; ks++) {
            const unsigned koff = soff + ks * 32;   // ks*16 elems * 2B
            unsigned aF[4][4], bF[4][2];
#pragma unroll
            for (int i = 0; i < 4; i++) {
                asm volatile(
                    "ldmatrix.sync.aligned.m8n8.x4.shared.b16 {%0,%1,%2,%3}, [%4];\n"
                    : "=r"(aF[i][0]), "=r"(aF[i][1]), "=r"(aF[i][2]), "=r"(aF[i][3])
                    : "r"(aBase[i] + koff));
            }
#pragma unroll
            for (int j = 0; j < 2; j++) {
                unsigned r0, r1, r2, r3;
                asm volatile(
                    "ldmatrix.sync.aligned.m8n8.x4.shared.b16 {%0,%1,%2,%3}, [%4];\n"
                    : "=r"(r0), "=r"(r1), "=r"(r2), "=r"(r3)
                    : "r"(bBase[j] + koff));
                bF[2 * j + 0][0] = r0; bF[2 * j + 0][1] = r1;
                bF[2 * j + 1][0] = r2; bF[2 * j + 1][1] = r3;
            }
#pragma unroll
            for (int i = 0; i < 4; i++)
#pragma unroll
                for (int j = 0; j < 4; j++) {
                    asm volatile(
                        "mma.sync.aligned.m16n8k16.row.col.f32.bf16.bf16.f32 "
                        "{%0,%1,%2,%3}, {%4,%5,%6,%7}, {%8,%9}, {%0,%1,%2,%3};\n"
                        : "+f"(acc[i][j][0]), "+f"(acc[i][j][1]),
                          "+f"(acc[i][j][2]), "+f"(acc[i][j][3])
                        : "r"(aF[i][0]), "r"(aF[i][1]),
                          "r"(aF[i][2]), "r"(aF[i][3]),
                          "r"(bF[j][0]), "r"(bF[j][1]));
                }
        }

        soff += STAGE_BYTES;
        if (soff == STAGES * STAGE_BYTES) soff = 0;
    }

    const int grp = lane >> 2;
    const int qd  = (lane & 3) * 2;
#pragma unroll
    for (int i = 0; i < 4; i++) {
#pragma unroll
        for (int half = 0; half < 2; half++) {
            int m = by * GBM + wm * 64 + i * 16 + grp + half * 8;
            size_t crow = (size_t)m * N;
            size_t grow = (size_t)m * MODC + gate_off;
#pragma unroll
            for (int j = 0; j < 4; j++) {
                int n = bx * GBN + wn * 32 + j * 8 + qd;
                float v0 = acc[i][j][half * 2 + 0];
                float v1 = acc[i][j][half * 2 + 1];
                if (bias) { v0 += bias[n]; v1 += bias[n + 1]; }
                if (EPI == 1) { v0 = gelu_exact(v0); v1 = gelu_exact(v1); }
                if (EPI == 1 || EPI == 3) {
                    bf16* C = (bf16*)Cout;
                    *(unsigned*)(C + crow + n) = pack_bf2(v0, v1);
                } else if (EPI == 2) {
                    float* C = (float*)Cout;
                    float g0 = __bfloat162float(gate[grow + n]);
                    float g1 = __bfloat162float(gate[grow + n + 1]);
                    C[crow + n]     = res[crow + n]     + g0 * v0;
                    C[crow + n + 1] = res[crow + n + 1] + g1 * v1;
                }
            }
        }
    }
}

// ---------------------------------------------------------------------------
// Tensor-core causal flash attention, diagonal-paired (unchanged from 442.9us)
// ---------------------------------------------------------------------------
#define ASTR 72
#define KVTILE (64 * ASTR)
#define ATTN_SMEM (3 * 2 * KVTILE * 2)    // 55296 B dynamic

__device__ __forceinline__ void attn_prefetch(
    const bf16* __restrict__ qkv, bf16* pool, int b, int h, int kt, int tid)
{
    bf16* Ks = pool + (kt % 3) * 2 * KVTILE;
    bf16* Vs = Ks + KVTILE;
    const int k0 = kt * 64;
#pragma unroll
    for (int it = 0; it < 4; it++) {
        int idx = tid + it * 128;
        int row = idx >> 3, c8 = (idx & 7) * 8;
        const bf16* src = qkv + (size_t)(b * Tt + k0 + row) * QKVC + h * 64 + c8;
        asm volatile("cp.async.cg.shared.global [%0], [%1], 16;\n"
                     :: "r"(smem_u32(&Ks[row * ASTR + c8])), "l"(src + 512));
        asm volatile("cp.async.cg.shared.global [%0], [%1], 16;\n"
                     :: "r"(smem_u32(&Vs[row * ASTR + c8])), "l"(src + 1024));
    }
    asm volatile("cp.async.commit_group;\n" ::: "memory");
}

__global__ void __launch_bounds__(128) attn_tc_kernel(
    const bf16* __restrict__ qkv, bf16* __restrict__ out)
{
    extern __shared__ bf16 pool[];
    const int b  = blockIdx.z, h = blockIdx.y, pair = blockIdx.x;
    const int tid = threadIdx.x, w = tid >> 5, lane = tid & 31;

#pragma unroll 1
    for (int hh = 0; hh < 2; hh++) {
        const int qt = hh ? (NQT - 1 - pair) : pair;

        __syncthreads();

#pragma unroll
        for (int it = 0; it < 8; it++) {
            int idx = tid + it * 128;
            int row = idx >> 3, c8 = (idx & 7) * 8;
            const bf16* src =
                qkv + (size_t)(b * Tt + qt * 128 + row) * QKVC + h * 64 + c8;
            asm volatile("cp.async.cg.shared.global [%0], [%1], 16;\n"
                         :: "r"(smem_u32(&pool[row * ASTR + c8])), "l"(src));
        }
        asm volatile("cp.async.commit_group;\n" ::: "memory");
        asm volatile("cp.async.wait_group 0;" ::: "memory");
        __syncthreads();

        unsigned qF[2][4][4];
#pragma unroll
        for (int i = 0; i < 2; i++)
#pragma unroll
            for (int kk = 0; kk < 4; kk++) {
                int row = w * 32 + i * 16 + (lane & 15);
                int col = kk * 16 + (lane >> 4) * 8;
                unsigned addr = smem_u32(&pool[row * ASTR + col]);
                asm volatile(
                    "ldmatrix.sync.aligned.m8n8.x4.shared.b16 {%0,%1,%2,%3}, [%4];\n"
                    : "=r"(qF[i][kk][0]), "=r"(qF[i][kk][1]),
                      "=r"(qF[i][kk][2]), "=r"(qF[i][kk][3])
                    : "r"(addr));
            }
        __syncthreads();

        float oAcc[2][8][4];
#pragma unroll
        for (int i = 0; i < 2; i++)
#pragma unroll
            for (int j = 0; j < 8; j++)
#pragma unroll
                for (int r = 0; r < 4; r++) oAcc[i][j][r] = 0.f;
        float lsum[2][2] = {{0.f, 0.f}, {0.f, 0.f}};

        const int qmax  = qt * 128 + w * 32 + 31;
        const int ntile = 2 * (qt + 1);

        attn_prefetch(qkv, pool, b, h, 0, tid);
        if (ntile > 1) attn_prefetch(qkv, pool, b, h, 1, tid);

        for (int kt = 0; kt < ntile; kt++) {
            if (kt + 1 >= ntile)
                asm volatile("cp.async.wait_group 0;" ::: "memory");
            else
                asm volatile("cp.async.wait_group 1;" ::: "memory");
            __syncthreads();

            if (kt + 2 < ntile) attn_prefetch(qkv, pool, b, h, kt + 2, tid);

            const bf16* Ks = pool + (kt % 3) * 2 * KVTILE;
            const bf16* Vs = Ks + KVTILE;
            const int k0 = kt * 64;

            if (k0 <= qmax) {
                float sAcc[2][8][4];
#pragma unroll
                for (int i = 0; i < 2; i++)
#pragma unroll
                    for (int j = 0; j < 8; j++)
#pragma unroll
                        for (int r = 0; r < 4; r++) sAcc[i][j][r] = 0.f;

#pragma unroll
                for (int kk = 0; kk < 4; kk++) {
#pragma unroll
                    for (int j2 = 0; j2 < 4; j2++) {
                        int row = j2 * 16 + (lane >> 4) * 8 + (lane & 7);
                        int col = kk * 16 + ((lane >> 3) & 1) * 8;
                        unsigned addr = smem_u32(&Ks[row * ASTR + col]);
                        unsigned r0, r1, r2, r3;
                        asm volatile(
                            "ldmatrix.sync.aligned.m8n8.x4.shared.b16 {%0,%1,%2,%3}, [%4];\n"
                            : "=r"(r0), "=r"(r1), "=r"(r2), "=r"(r3) : "r"(addr));
#pragma unroll
                        for (int i = 0; i < 2; i++) {
                            asm volatile(
                                "mma.sync.aligned.m16n8k16.row.col.f32.bf16.bf16.f32 "
                                "{%0,%1,%2,%3}, {%4,%5,%6,%7}, {%8,%9}, {%0,%1,%2,%3};\n"
                                : "+f"(sAcc[i][2*j2][0]), "+f"(sAcc[i][2*j2][1]),
                                  "+f"(sAcc[i][2*j2][2]), "+f"(sAcc[i][2*j2][3])
                                : "r"(qF[i][kk][0]), "r"(qF[i][kk][1]),
                                  "r"(qF[i][kk][2]), "r"(qF[i][kk][3]),
                                  "r"(r0), "r"(r1));
                            asm volatile(
                                "mma.sync.aligned.m16n8k16.row.col.f32.bf16.bf16.f32 "
                                "{%0,%1,%2,%3}, {%4,%5,%6,%7}, {%8,%9}, {%0,%1,%2,%3};\n"
                                : "+f"(sAcc[i][2*j2+1][0]), "+f"(sAcc[i][2*j2+1][1]),
                                  "+f"(sAcc[i][2*j2+1][2]), "+f"(sAcc[i][2*j2+1][3])
                                : "r"(qF[i][kk][0]), "r"(qF[i][kk][1]),
                                  "r"(qF[i][kk][2]), "r"(qF[i][kk][3]),
                                  "r"(r2), "r"(r3));
                        }
                    }
                }

                const int qrow0 = qt * 128 + w * 32 + (lane >> 2);
#pragma unroll
                for (int i = 0; i < 2; i++) {
                    int q0 = qrow0 + i * 16;
                    int q1 = q0 + 8;
#pragma unroll
                    for (int j = 0; j < 8; j++) {
                        int kc = k0 + j * 8 + (lane & 3) * 2;
                        float p0 = (kc     <= q0) ? fast_exp(sAcc[i][j][0] * 0.125f) : 0.f;
                        float p1 = (kc + 1 <= q0) ? fast_exp(sAcc[i][j][1] * 0.125f) : 0.f;
                        float p2 = (kc     <= q1) ? fast_exp(sAcc[i][j][2] * 0.125f) : 0.f;
                        float p3 = (kc + 1 <= q1) ? fast_exp(sAcc[i][j][3] * 0.125f) : 0.f;
                        sAcc[i][j][0] = p0; sAcc[i][j][1] = p1;
                        sAcc[i][j][2] = p2; sAcc[i][j][3] = p3;
                        lsum[i][0] += p0 + p1;
                        lsum[i][1] += p2 + p3;
                    }
                }

#pragma unroll
                for (int c = 0; c < 4; c++) {
                    unsigned pF[2][4];
#pragma unroll
                    for (int i = 0; i < 2; i++) {
                        pF[i][0] = pack_bf2(sAcc[i][2*c  ][0], sAcc[i][2*c  ][1]);
                        pF[i][1] = pack_bf2(sAcc[i][2*c  ][2], sAcc[i][2*c  ][3]);
                        pF[i][2] = pack_bf2(sAcc[i][2*c+1][0], sAcc[i][2*c+1][1]);
                        pF[i][3] = pack_bf2(sAcc[i][2*c+1][2], sAcc[i][2*c+1][3]);
                    }
#pragma unroll
                    for (int d2 = 0; d2 < 4; d2++) {
                        int g = lane >> 3;
                        int row = c * 16 + (g & 1) * 8 + (lane & 7);
                        int col = d2 * 16 + (g >> 1) * 8;
                        unsigned addr = smem_u32(&Vs[row * ASTR + col]);
                        unsigned v0, v1, v2, v3;
                        asm volatile(
                            "ldmatrix.sync.aligned.m8n8.x4.trans.shared.b16 {%0,%1,%2,%3}, [%4];\n"
                            : "=r"(v0), "=r"(v1), "=r"(v2), "=r"(v3) : "r"(addr));
#pragma unroll
                        for (int i = 0; i < 2; i++) {
                            asm volatile(
                                "mma.sync.aligned.m16n8k16.row.col.f32.bf16.bf16.f32 "
                                "{%0,%1,%2,%3}, {%4,%5,%6,%7}, {%8,%9}, {%0,%1,%2,%3};\n"
                                : "+f"(oAcc[i][2*d2][0]), "+f"(oAcc[i][2*d2][1]),
                                  "+f"(oAcc[i][2*d2][2]), "+f"(oAcc[i][2*d2][3])
                                : "r"(pF[i][0]), "r"(pF[i][1]), "r"(pF[i][2]), "r"(pF[i][3]),
                                  "r"(v0), "r"(v1));
                            asm volatile(
                                "mma.sync.aligned.m16n8k16.row.col.f32.bf16.bf16.f32 "
                                "{%0,%1,%2,%3}, {%4,%5,%6,%7}, {%8,%9}, {%0,%1,%2,%3};\n"
                                : "+f"(oAcc[i][2*d2+1][0]), "+f"(oAcc[i][2*d2+1][1]),
                                  "+f"(oAcc[i][2*d2+1][2]), "+f"(oAcc[i][2*d2+1][3])
                                : "r"(pF[i][0]), "r"(pF[i][1]), "r"(pF[i][2]), "r"(pF[i][3]),
                                  "r"(v2), "r"(v3));
                        }
                    }
                }
            }
        }

#pragma unroll
        for (int i = 0; i < 2; i++) {
#pragma unroll
            for (int hf = 0; hf < 2; hf++) {
                float l = lsum[i][hf];
                l += __shfl_xor_sync(0xffffffffu, l, 1);
                l += __shfl_xor_sync(0xffffffffu, l, 2);
                float inv = 1.0f / l;
                int qg = qt * 128 + w * 32 + i * 16 + (lane >> 2) + hf * 8;
                bf16* orow = out + (size_t)(b * Tt + qg) * DIMd + h * DHEAD;
#pragma unroll
                for (int j = 0; j < 8; j++) {
                    int d = j * 8 + (lane & 3) * 2;
                    *(unsigned*)(orow + d) =
                        pack_bf2(oAcc[i][j][hf * 2] * inv, oAcc[i][j][hf * 2 + 1] * inv);
                }
            }
        }
    }
}

// ---------------------------------------------------------------------------
// Launch
// Inputs: 0:x 1:action_emb 2:causal_mask 3:Wqkv 4:Wout 5:bout
//         6:W1 7:b1 8:W2 9:b2 10:Wmod 11:bmod
// ---------------------------------------------------------------------------
extern "C" void kernel_launch(void* const* d_in, const int* in_sizes, int n_in,
                              void* d_out, int out_size)
{
    const float* x    = (const float*)d_in[0];
    const float* aemb = (const float*)d_in[1];
    const float* Wqkv = (const float*)d_in[3];
    const float* Wout = (const float*)d_in[4];
    const float* bout = (const float*)d_in[5];
    const float* W1   = (const float*)d_in[6];
    const float* b1   = (const float*)d_in[7];
    const float* W2   = (const float*)d_in[8];
    const float* b2   = (const float*)d_in[9];
    const float* Wmod = (const float*)d_in[10];
    const float* bmod = (const float*)d_in[11];
    float* out = (float*)d_out;

    float *x1_p;
    bf16 *mod_p, *silu_p, *h_p, *qkv_p, *attn_p, *mlp_p;
    bf16 *wqkv_p, *wout_p, *w1_p, *w2_p, *wmod_p;
    cudaGetSymbolAddress((void**)&x1_p,   g_x1);
    cudaGetSymbolAddress((void**)&mod_p,  g_mod_bf);
    cudaGetSymbolAddress((void**)&silu_p, g_silu_bf);
    cudaGetSymbolAddress((void**)&h_p,    g_h_bf);
    cudaGetSymbolAddress((void**)&qkv_p,  g_qkv_bf);
    cudaGetSymbolAddress((void**)&attn_p, g_attn_bf);
    cudaGetSymbolAddress((void**)&mlp_p,  g_mlp_bf);
    cudaGetSymbolAddress((void**)&wqkv_p, g_Wqkv_bf);
    cudaGetSymbolAddress((void**)&wout_p, g_Wout_bf);
    cudaGetSymbolAddress((void**)&w1_p,   g_W1_bf);
    cudaGetSymbolAddress((void**)&w2_p,   g_W2_bf);
    cudaGetSymbolAddress((void**)&wmod_p, g_Wmod_bf);

    cudaFuncSetAttribute(mma_gemm<1>, cudaFuncAttributeMaxDynamicSharedMemorySize, GEMM_SMEM);
    cudaFuncSetAttribute(mma_gemm<2>, cudaFuncAttributeMaxDynamicSharedMemorySize, GEMM_SMEM);
    cudaFuncSetAttribute(mma_gemm<3>, cudaFuncAttributeMaxDynamicSharedMemorySize, GEMM_SMEM);
    cudaFuncSetAttribute(attn_tc_kernel, cudaFuncAttributeMaxDynamicSharedMemorySize, ATTN_SMEM);

    // 1) fused prologue
    prep_kernel<<<(P_S5 + 255) / 256, 256>>>(
        aemb, Wqkv, Wout, W1, W2, Wmod,
        silu_p, wqkv_p, wout_p, w1_p, w2_p, wmod_p);

    // 2) mod = silu_a @ Wmod^T + bmod -> bf16
    mma_gemm<3><<<dim3(MODC / GBN, NTOK / GBM), 256, GEMM_SMEM>>>(
        silu_p, wmod_p, bmod, nullptr, nullptr, 0, mod_p, NTOK, MODC, ADIM);

    // 3) h = LN(x)*(1+scale1)+shift1 -> bf16
    lnmod_kernel<<<NTOK, 128>>>(x, mod_p, 0, DIMd, h_p);

    // 4) qkv = h @ Wqkv^T -> bf16
    mma_gemm<3><<<dim3(QKVC / GBN, NTOK / GBM), 256, GEMM_SMEM>>>(
        h_p, wqkv_p, nullptr, nullptr, nullptr, 0, qkv_p, NTOK, QKVC, DIMd);

    // 5) tensor-core causal attention (diagonal-paired) -> bf16
    attn_tc_kernel<<<dim3(NQT / 2, NHEAD, Bb), 128, ATTN_SMEM>>>(qkv_p, attn_p);

    // 6) x1 = x + gate1 * (attn @ Wout^T + bout)  fp32 out
    mma_gemm<2><<<dim3(DIMd / GBN, NTOK / GBM), 256, GEMM_SMEM>>>(
        attn_p, wout_p, bout, x, mod_p, 2 * DIMd, x1_p, NTOK, DIMd, DIMd);

    // 7) h = LN(x1)*(1+scale2)+shift2 -> bf16
    lnmod_kernel<<<NTOK, 128>>>(x1_p, mod_p, 3 * DIMd, 4 * DIMd, h_p);

    // 8) mlp = gelu(h @ W1^T + b1) -> bf16
    mma_gemm<1><<<dim3(MLPD / GBN, NTOK / GBM), 256, GEMM_SMEM>>>(
        h_p, w1_p, b1, nullptr, nullptr, 0, mlp_p, NTOK, MLPD, DIMd);

    // 9) out = x1 + gate2 * (mlp @ W2^T + b2)  fp32 out
    mma_gemm<2><<<dim3(DIMd / GBN, NTOK / GBM), 256, GEMM_SMEM>>>(
        mlp_p, w2_p, b2, x1_p, mod_p, 5 * DIMd, out, NTOK, DIMd, MLPD);
}

// round 16
// speedup vs baseline: 1.0879x; 1.0145x over previous
#include <cuda_runtime.h>
#include <cuda_bf16.h>
#include <math.h>

// Problem constants
#define Bb     4
#define Tt     2048
#define DIMd   512
#define NHEAD  8
#define DHEAD  64
#define MLPD   2048
#define ADIM   256
#define NTOK   (Bb * Tt)
#define MODC   (6 * DIMd)
#define QKVC   (3 * DIMd)
#define NQT    (Tt / 128)          // 16 q-tiles

typedef __nv_bfloat16 bf16;

// ---------------------------------------------------------------------------
// Scratch (static device globals; allocation-free per harness rules)
// ---------------------------------------------------------------------------
__device__ __align__(256) float g_x1 [NTOK * DIMd];          // fp32 residual

__device__ __align__(256) bf16 g_mod_bf [(size_t)NTOK * MODC];
__device__ __align__(256) bf16 g_silu_bf[NTOK * ADIM];
__device__ __align__(256) bf16 g_h_bf   [NTOK * DIMd];
__device__ __align__(256) bf16 g_qkv_bf [(size_t)NTOK * QKVC];
__device__ __align__(256) bf16 g_attn_bf[NTOK * DIMd];
__device__ __align__(256) bf16 g_mlp_bf [(size_t)NTOK * MLPD];

__device__ __align__(256) bf16 g_Wqkv_bf[QKVC * DIMd];
__device__ __align__(256) bf16 g_Wout_bf[DIMd * DIMd];
__device__ __align__(256) bf16 g_W1_bf  [MLPD * DIMd];
__device__ __align__(256) bf16 g_W2_bf  [DIMd * MLPD];
__device__ __align__(256) bf16 g_Wmod_bf[MODC * ADIM];

// ---------------------------------------------------------------------------
// Helpers
// ---------------------------------------------------------------------------
__device__ __forceinline__ unsigned smem_u32(const void* p)
{
    return (unsigned)__cvta_generic_to_shared(p);
}
__device__ __forceinline__ unsigned pack_bf2(float a, float b)
{
    __nv_bfloat162 t = __floats2bfloat162_rn(a, b);
    return *(unsigned*)&t;
}
__device__ __forceinline__ float gelu_exact(float v)
{
    return 0.5f * v * (1.0f + erff(v * 0.70710678118654752f));
}
__device__ __forceinline__ float fast_exp(float x)
{
    float y = x * 1.44269504088896f;
    y = fminf(fmaxf(y, -60.0f), 60.0f);
    float t = y + 12582912.0f;
    float f = y - (t - 12582912.0f);
    int   n = __float_as_int(t) - 0x4B400000;
    float p = 1.33336499e-3f;
    p = fmaf(p, f, 9.61817249e-3f);
    p = fmaf(p, f, 5.55036863e-2f);
    p = fmaf(p, f, 2.40226507e-1f);
    p = fmaf(p, f, 6.93147182e-1f);
    p = fmaf(p, f, 1.0f);
    return p * __int_as_float((n + 127) << 23);
}

// ---------------------------------------------------------------------------
// Fused prologue: all 5 weight conversions + SiLU in ONE launch.
// ---------------------------------------------------------------------------
#define P_S0 (NTOK * ADIM / 4)
#define P_S1 (P_S0 + QKVC * DIMd / 4)
#define P_S2 (P_S1 + DIMd * DIMd / 4)
#define P_S3 (P_S2 + MLPD * DIMd / 4)
#define P_S4 (P_S3 + DIMd * MLPD / 4)
#define P_S5 (P_S4 + MODC * ADIM / 4)

__global__ void prep_kernel(
    const float* __restrict__ aemb, const float* __restrict__ Wqkv,
    const float* __restrict__ Wout, const float* __restrict__ W1,
    const float* __restrict__ W2,   const float* __restrict__ Wmod,
    bf16* __restrict__ silu_o, bf16* __restrict__ wqkv_o,
    bf16* __restrict__ wout_o, bf16* __restrict__ w1_o,
    bf16* __restrict__ w2_o,   bf16* __restrict__ wmod_o)
{
    int i = blockIdx.x * blockDim.x + threadIdx.x;
    const float* src; bf16* dst; int base; bool is_silu = false;
    if      (i < P_S0) { src = aemb; dst = silu_o; base = i;        is_silu = true; }
    else if (i < P_S1) { src = Wqkv; dst = wqkv_o; base = i - P_S0; }
    else if (i < P_S2) { src = Wout; dst = wout_o; base = i - P_S1; }
    else if (i < P_S3) { src = W1;   dst = w1_o;   base = i - P_S2; }
    else if (i < P_S4) { src = W2;   dst = w2_o;   base = i - P_S3; }
    else if (i < P_S5) { src = Wmod; dst = wmod_o; base = i - P_S4; }
    else return;
    float4 v = ((const float4*)src)[base];
    if (is_silu) {
        v.x = v.x / (1.0f + __expf(-v.x));
        v.y = v.y / (1.0f + __expf(-v.y));
        v.z = v.z / (1.0f + __expf(-v.z));
        v.w = v.w / (1.0f + __expf(-v.w));
    }
    uint2 o;
    o.x = pack_bf2(v.x, v.y);
    o.y = pack_bf2(v.z, v.w);
    ((uint2*)dst)[base] = o;
}

// ---------------------------------------------------------------------------
// Fused LayerNorm + AdaLN modulation -> bf16
// ---------------------------------------------------------------------------
__global__ void lnmod_kernel(const float* __restrict__ x,
                             const bf16* __restrict__ mod,
                             int shift_off, int scale_off,
                             bf16* __restrict__ out)
{
    int row = blockIdx.x;
    int t   = threadIdx.x;
    const float* xr = x + (size_t)row * DIMd;

    float v[4];
    float s1 = 0.f, s2 = 0.f;
#pragma unroll
    for (int j = 0; j < 4; j++) {
        float z = xr[t + j * 128];
        v[j] = z; s1 += z; s2 += z * z;
    }
#pragma unroll
    for (int off = 16; off; off >>= 1) {
        s1 += __shfl_xor_sync(0xffffffffu, s1, off);
        s2 += __shfl_xor_sync(0xffffffffu, s2, off);
    }
    __shared__ float r1[4], r2[4];
    int w = t >> 5;
    if ((t & 31) == 0) { r1[w] = s1; r2[w] = s2; }
    __syncthreads();
    s1 = r1[0] + r1[1] + r1[2] + r1[3];
    s2 = r2[0] + r2[1] + r2[2] + r2[3];

    float mu   = s1 * (1.0f / DIMd);
    float var  = s2 * (1.0f / DIMd) - mu * mu;
    float rstd = rsqrtf(var + 1e-5f);

    const bf16* mrow = mod + (size_t)row * MODC;
    bf16* orow = out + (size_t)row * DIMd;
#pragma unroll
    for (int j = 0; j < 4; j++) {
        int c = t + j * 128;
        float sc = __bfloat162float(mrow[scale_off + c]);
        float sh = __bfloat162float(mrow[shift_off + c]);
        orow[c] = __float2bfloat16((v[j] - mu) * rstd * (1.0f + sc) + sh);
    }
}

// ---------------------------------------------------------------------------
// bf16 tensor-core GEMM: 128x128x64 tiles, 3-stage cp.async pipeline,
// one __syncthreads per 64-K tile, precomputed ldmatrix bases, and
// REGISTER-DOUBLE-BUFFERED fragments: __launch_bounds__(256,2) unlocks the
// 128-reg/thread budget (64K RF / 512 thr) so ks+1's ldmatrix issues while
// ks's 16 MMAs drain, hiding LDSM latency.
// EPI: 1 = GELU(acc+bias) bf16, 2 = res + gate*(acc+bias) fp32, 3 = acc(+bias) bf16
// ---------------------------------------------------------------------------
#define GBM 128
#define GBN 128
#define GBK 64
#define GSTR (GBK + 8)
#define STAGES 3
#define STAGE_ELEMS (2 * GBM * GSTR)
#define STAGE_BYTES (STAGE_ELEMS * 2)
#define GEMM_SMEM (STAGES * STAGE_BYTES)       // 110592 B

__device__ __forceinline__ void g2s_tile(
    const bf16* __restrict__ Ag, const bf16* __restrict__ Bg,
    int K, int kt, bf16* smemBuf, int lr, int lc)
{
    bf16* As = smemBuf + (kt % STAGES) * STAGE_ELEMS;
    bf16* Bs = As + GBM * GSTR;
    const int k0 = kt * GBK;
#pragma unroll
    for (int p = 0; p < 4; p++) {
        int row = lr + p * 32;
        unsigned sA = smem_u32(&As[row * GSTR + lc]);
        asm volatile("cp.async.cg.shared.global [%0], [%1], 16;\n"
                     :: "r"(sA), "l"(Ag + (size_t)row * K + k0 + lc));
        unsigned sB = smem_u32(&Bs[row * GSTR + lc]);
        asm volatile("cp.async.cg.shared.global [%0], [%1], 16;\n"
                     :: "r"(sB), "l"(Bg + (size_t)row * K + k0 + lc));
    }
    asm volatile("cp.async.commit_group;\n" ::: "memory");
}

__device__ __forceinline__ void ld_frags(
    const unsigned aBase[4], const unsigned bBase[2], unsigned koff,
    unsigned aF[4][4], unsigned bF[4][2])
{
#pragma unroll
    for (int i = 0; i < 4; i++) {
        asm volatile(
            "ldmatrix.sync.aligned.m8n8.x4.shared.b16 {%0,%1,%2,%3}, [%4];\n"
            : "=r"(aF[i][0]), "=r"(aF[i][1]), "=r"(aF[i][2]), "=r"(aF[i][3])
            : "r"(aBase[i] + koff));
    }
#pragma unroll
    for (int j = 0; j < 2; j++) {
        unsigned r0, r1, r2, r3;
        asm volatile(
            "ldmatrix.sync.aligned.m8n8.x4.shared.b16 {%0,%1,%2,%3}, [%4];\n"
            : "=r"(r0), "=r"(r1), "=r"(r2), "=r"(r3)
            : "r"(bBase[j] + koff));
        bF[2 * j + 0][0] = r0; bF[2 * j + 0][1] = r1;
        bF[2 * j + 1][0] = r2; bF[2 * j + 1][1] = r3;
    }
}

template <int EPI>
__global__ void __launch_bounds__(256, 2) mma_gemm(
    const bf16* __restrict__ A,
    const bf16* __restrict__ Bw,
    const float* __restrict__ bias,
    const float* __restrict__ res,
    const bf16* __restrict__ gate, int gate_off,
    void* __restrict__ Cout,
    int M, int N, int K)
{
    extern __shared__ bf16 smemBuf[];

    const int tid  = threadIdx.x;
    const int bx   = blockIdx.x, by = blockIdx.y;
    const int wid  = tid >> 5, lane = tid & 31;
    const int wm   = wid & 1;
    const int wn   = wid >> 1;

    const int lr = tid >> 3;
    const int lc = (tid & 7) * 8;
    const bf16* Ag = A  + (size_t)(by * GBM) * K;
    const bf16* Bg = Bw + (size_t)(bx * GBN) * K;

    // Precomputed ldmatrix base addresses (stage 0, ks 0), bytes.
    unsigned aBase[4], bBase[2];
#pragma unroll
    for (int i = 0; i < 4; i++) {
        int row = wm * 64 + i * 16 + (lane & 15);
        int col = (lane >> 4) * 8;
        aBase[i] = smem_u32(&smemBuf[row * GSTR + col]);
    }
#pragma unroll
    for (int j = 0; j < 2; j++) {
        int row = wn * 32 + j * 16 + (lane >> 4) * 8 + (lane & 7);
        int col = ((lane >> 3) & 1) * 8;
        bBase[j] = smem_u32(&smemBuf[GBM * GSTR + row * GSTR + col]);
    }

    float acc[4][4][4];
#pragma unroll
    for (int i = 0; i < 4; i++)
#pragma unroll
        for (int j = 0; j < 4; j++)
#pragma unroll
            for (int r = 0; r < 4; r++) acc[i][j][r] = 0.f;

    const int KT = K / GBK;

    g2s_tile(Ag, Bg, K, 0, smemBuf, lr, lc);
    g2s_tile(Ag, Bg, K, 1, smemBuf, lr, lc);

    unsigned soff = 0;
    for (int kt = 0; kt < KT; kt++) {
        if (kt + 1 >= KT)
            asm volatile("cp.async.wait_group 0;" ::: "memory");
        else
            asm volatile("cp.async.wait_group 1;" ::: "memory");
        __syncthreads();

        if (kt + 2 < KT) g2s_tile(Ag, Bg, K, kt + 2, smemBuf, lr, lc);

        // Software-pipelined fragment double buffer across ks steps.
        unsigned aF[2][4][4], bF[2][4][2];
        ld_frags(aBase, bBase, soff, aF[0], bF[0]);
#pragma unroll
        for (int ks = 0; ks < 4; ks++) {
            const int cur = ks & 1;
            if (ks < 3)
                ld_frags(aBase, bBase, soff + (ks + 1) * 32,
                         aF[cur ^ 1], bF[cur ^ 1]);
#pragma unroll
            for (int i = 0; i < 4; i++)
#pragma unroll
                for (int j = 0; j < 4; j++) {
                    asm volatile(
                        "mma.sync.aligned.m16n8k16.row.col.f32.bf16.bf16.f32 "
                        "{%0,%1,%2,%3}, {%4,%5,%6,%7}, {%8,%9}, {%0,%1,%2,%3};\n"
                        : "+f"(acc[i][j][0]), "+f"(acc[i][j][1]),
                          "+f"(acc[i][j][2]), "+f"(acc[i][j][3])
                        : "r"(aF[cur][i][0]), "r"(aF[cur][i][1]),
                          "r"(aF[cur][i][2]), "r"(aF[cur][i][3]),
                          "r"(bF[cur][j][0]), "r"(bF[cur][j][1]));
                }
        }

        soff += STAGE_BYTES;
        if (soff == STAGES * STAGE_BYTES) soff = 0;
    }

    const int grp = lane >> 2;
    const int qd  = (lane & 3) * 2;
#pragma unroll
    for (int i = 0; i < 4; i++) {
#pragma unroll
        for (int half = 0; half < 2; half++) {
            int m = by * GBM + wm * 64 + i * 16 + grp + half * 8;
            size_t crow = (size_t)m * N;
            size_t grow = (size_t)m * MODC + gate_off;
#pragma unroll
            for (int j = 0; j < 4; j++) {
                int n = bx * GBN + wn * 32 + j * 8 + qd;
                float v0 = acc[i][j][half * 2 + 0];
                float v1 = acc[i][j][half * 2 + 1];
                if (bias) { v0 += bias[n]; v1 += bias[n + 1]; }
                if (EPI == 1) { v0 = gelu_exact(v0); v1 = gelu_exact(v1); }
                if (EPI == 1 || EPI == 3) {
                    bf16* C = (bf16*)Cout;
                    *(unsigned*)(C + crow + n) = pack_bf2(v0, v1);
                } else if (EPI == 2) {
                    float* C = (float*)Cout;
                    float g0 = __bfloat162float(gate[grow + n]);
                    float g1 = __bfloat162float(gate[grow + n + 1]);
                    C[crow + n]     = res[crow + n]     + g0 * v0;
                    C[crow + n + 1] = res[crow + n + 1] + g1 * v1;
                }
            }
        }
    }
}

// ---------------------------------------------------------------------------
// Tensor-core causal flash attention, diagonal-paired (unchanged)
// ---------------------------------------------------------------------------
#define ASTR 72
#define KVTILE (64 * ASTR)
#define ATTN_SMEM (3 * 2 * KVTILE * 2)    // 55296 B dynamic

__device__ __forceinline__ void attn_prefetch(
    const bf16* __restrict__ qkv, bf16* pool, int b, int h, int kt, int tid)
{
    bf16* Ks = pool + (kt % 3) * 2 * KVTILE;
    bf16* Vs = Ks + KVTILE;
    const int k0 = kt * 64;
#pragma unroll
    for (int it = 0; it < 4; it++) {
        int idx = tid + it * 128;
        int row = idx >> 3, c8 = (idx & 7) * 8;
        const bf16* src = qkv + (size_t)(b * Tt + k0 + row) * QKVC + h * 64 + c8;
        asm volatile("cp.async.cg.shared.global [%0], [%1], 16;\n"
                     :: "r"(smem_u32(&Ks[row * ASTR + c8])), "l"(src + 512));
        asm volatile("cp.async.cg.shared.global [%0], [%1], 16;\n"
                     :: "r"(smem_u32(&Vs[row * ASTR + c8])), "l"(src + 1024));
    }
    asm volatile("cp.async.commit_group;\n" ::: "memory");
}

__global__ void __launch_bounds__(128) attn_tc_kernel(
    const bf16* __restrict__ qkv, bf16* __restrict__ out)
{
    extern __shared__ bf16 pool[];
    const int b  = blockIdx.z, h = blockIdx.y, pair = blockIdx.x;
    const int tid = threadIdx.x, w = tid >> 5, lane = tid & 31;

#pragma unroll 1
    for (int hh = 0; hh < 2; hh++) {
        const int qt = hh ? (NQT - 1 - pair) : pair;

        __syncthreads();

#pragma unroll
        for (int it = 0; it < 8; it++) {
            int idx = tid + it * 128;
            int row = idx >> 3, c8 = (idx & 7) * 8;
            const bf16* src =
                qkv + (size_t)(b * Tt + qt * 128 + row) * QKVC + h * 64 + c8;
            asm volatile("cp.async.cg.shared.global [%0], [%1], 16;\n"
                         :: "r"(smem_u32(&pool[row * ASTR + c8])), "l"(src));
        }
        asm volatile("cp.async.commit_group;\n" ::: "memory");
        asm volatile("cp.async.wait_group 0;" ::: "memory");
        __syncthreads();

        unsigned qF[2][4][4];
#pragma unroll
        for (int i = 0; i < 2; i++)
#pragma unroll
            for (int kk = 0; kk < 4; kk++) {
                int row = w * 32 + i * 16 + (lane & 15);
                int col = kk * 16 + (lane >> 4) * 8;
                unsigned addr = smem_u32(&pool[row * ASTR + col]);
                asm volatile(
                    "ldmatrix.sync.aligned.m8n8.x4.shared.b16 {%0,%1,%2,%3}, [%4];\n"
                    : "=r"(qF[i][kk][0]), "=r"(qF[i][kk][1]),
                      "=r"(qF[i][kk][2]), "=r"(qF[i][kk][3])
                    : "r"(addr));
            }
        __syncthreads();

        float oAcc[2][8][4];
#pragma unroll
        for (int i = 0; i < 2; i++)
#pragma unroll
            for (int j = 0; j < 8; j++)
#pragma unroll
                for (int r = 0; r < 4; r++) oAcc[i][j][r] = 0.f;
        float lsum[2][2] = {{0.f, 0.f}, {0.f, 0.f}};

        const int qmax  = qt * 128 + w * 32 + 31;
        const int ntile = 2 * (qt + 1);

        attn_prefetch(qkv, pool, b, h, 0, tid);
        if (ntile > 1) attn_prefetch(qkv, pool, b, h, 1, tid);

        for (int kt = 0; kt < ntile; kt++) {
            if (kt + 1 >= ntile)
                asm volatile("cp.async.wait_group 0;" ::: "memory");
            else
                asm volatile("cp.async.wait_group 1;" ::: "memory");
            __syncthreads();

            if (kt + 2 < ntile) attn_prefetch(qkv, pool, b, h, kt + 2, tid);

            const bf16* Ks = pool + (kt % 3) * 2 * KVTILE;
            const bf16* Vs = Ks + KVTILE;
            const int k0 = kt * 64;

            if (k0 <= qmax) {
                float sAcc[2][8][4];
#pragma unroll
                for (int i = 0; i < 2; i++)
#pragma unroll
                    for (int j = 0; j < 8; j++)
#pragma unroll
                        for (int r = 0; r < 4; r++) sAcc[i][j][r] = 0.f;

#pragma unroll
                for (int kk = 0; kk < 4; kk++) {
#pragma unroll
                    for (int j2 = 0; j2 < 4; j2++) {
                        int row = j2 * 16 + (lane >> 4) * 8 + (lane & 7);
                        int col = kk * 16 + ((lane >> 3) & 1) * 8;
                        unsigned addr = smem_u32(&Ks[row * ASTR + col]);
                        unsigned r0, r1, r2, r3;
                        asm volatile(
                            "ldmatrix.sync.aligned.m8n8.x4.shared.b16 {%0,%1,%2,%3}, [%4];\n"
                            : "=r"(r0), "=r"(r1), "=r"(r2), "=r"(r3) : "r"(addr));
#pragma unroll
                        for (int i = 0; i < 2; i++) {
                            asm volatile(
                                "mma.sync.aligned.m16n8k16.row.col.f32.bf16.bf16.f32 "
                                "{%0,%1,%2,%3}, {%4,%5,%6,%7}, {%8,%9}, {%0,%1,%2,%3};\n"
                                : "+f"(sAcc[i][2*j2][0]), "+f"(sAcc[i][2*j2][1]),
                                  "+f"(sAcc[i][2*j2][2]), "+f"(sAcc[i][2*j2][3])
                                : "r"(qF[i][kk][0]), "r"(qF[i][kk][1]),
                                  "r"(qF[i][kk][2]), "r"(qF[i][kk][3]),
                                  "r"(r0), "r"(r1));
                            asm volatile(
                                "mma.sync.aligned.m16n8k16.row.col.f32.bf16.bf16.f32 "
                                "{%0,%1,%2,%3}, {%4,%5,%6,%7}, {%8,%9}, {%0,%1,%2,%3};\n"
                                : "+f"(sAcc[i][2*j2+1][0]), "+f"(sAcc[i][2*j2+1][1]),
                                  "+f"(sAcc[i][2*j2+1][2]), "+f"(sAcc[i][2*j2+1][3])
                                : "r"(qF[i][kk][0]), "r"(qF[i][kk][1]),
                                  "r"(qF[i][kk][2]), "r"(qF[i][kk][3]),
                                  "r"(r2), "r"(r3));
                        }
                    }
                }

                const int qrow0 = qt * 128 + w * 32 + (lane >> 2);
#pragma unroll
                for (int i = 0; i < 2; i++) {
                    int q0 = qrow0 + i * 16;
                    int q1 = q0 + 8;
#pragma unroll
                    for (int j = 0; j < 8; j++) {
                        int kc = k0 + j * 8 + (lane & 3) * 2;
                        float p0 = (kc     <= q0) ? fast_exp(sAcc[i][j][0] * 0.125f) : 0.f;
                        float p1 = (kc + 1 <= q0) ? fast_exp(sAcc[i][j][1] * 0.125f) : 0.f;
                        float p2 = (kc     <= q1) ? fast_exp(sAcc[i][j][2] * 0.125f) : 0.f;
                        float p3 = (kc + 1 <= q1) ? fast_exp(sAcc[i][j][3] * 0.125f) : 0.f;
                        sAcc[i][j][0] = p0; sAcc[i][j][1] = p1;
                        sAcc[i][j][2] = p2; sAcc[i][j][3] = p3;
                        lsum[i][0] += p0 + p1;
                        lsum[i][1] += p2 + p3;
                    }
                }

#pragma unroll
                for (int c = 0; c < 4; c++) {
                    unsigned pF[2][4];
#pragma unroll
                    for (int i = 0; i < 2; i++) {
                        pF[i][0] = pack_bf2(sAcc[i][2*c  ][0], sAcc[i][2*c  ][1]);
                        pF[i][1] = pack_bf2(sAcc[i][2*c  ][2], sAcc[i][2*c  ][3]);
                        pF[i][2] = pack_bf2(sAcc[i][2*c+1][0], sAcc[i][2*c+1][1]);
                        pF[i][3] = pack_bf2(sAcc[i][2*c+1][2], sAcc[i][2*c+1][3]);
                    }
#pragma unroll
                    for (int d2 = 0; d2 < 4; d2++) {
                        int g = lane >> 3;
                        int row = c * 16 + (g & 1) * 8 + (lane & 7);
                        int col = d2 * 16 + (g >> 1) * 8;
                        unsigned addr = smem_u32(&Vs[row * ASTR + col]);
                        unsigned v0, v1, v2, v3;
                        asm volatile(
                            "ldmatrix.sync.aligned.m8n8.x4.trans.shared.b16 {%0,%1,%2,%3}, [%4];\n"
                            : "=r"(v0), "=r"(v1), "=r"(v2), "=r"(v3) : "r"(addr));
#pragma unroll
                        for (int i = 0; i < 2; i++) {
                            asm volatile(
                                "mma.sync.aligned.m16n8k16.row.col.f32.bf16.bf16.f32 "
                                "{%0,%1,%2,%3}, {%4,%5,%6,%7}, {%8,%9}, {%0,%1,%2,%3};\n"
                                : "+f"(oAcc[i][2*d2][0]), "+f"(oAcc[i][2*d2][1]),
                                  "+f"(oAcc[i][2*d2][2]), "+f"(oAcc[i][2*d2][3])
                                : "r"(pF[i][0]), "r"(pF[i][1]), "r"(pF[i][2]), "r"(pF[i][3]),
                                  "r"(v0), "r"(v1));
                            asm volatile(
                                "mma.sync.aligned.m16n8k16.row.col.f32.bf16.bf16.f32 "
                                "{%0,%1,%2,%3}, {%4,%5,%6,%7}, {%8,%9}, {%0,%1,%2,%3};\n"
                                : "+f"(oAcc[i][2*d2+1][0]), "+f"(oAcc[i][2*d2+1][1]),
                                  "+f"(oAcc[i][2*d2+1][2]), "+f"(oAcc[i][2*d2+1][3])
                                : "r"(pF[i][0]), "r"(pF[i][1]), "r"(pF[i][2]), "r"(pF[i][3]),
                                  "r"(v2), "r"(v3));
                        }
                    }
                }
            }
        }

#pragma unroll
        for (int i = 0; i < 2; i++) {
#pragma unroll
            for (int hf = 0; hf < 2; hf++) {
                float l = lsum[i][hf];
                l += __shfl_xor_sync(0xffffffffu, l, 1);
                l += __shfl_xor_sync(0xffffffffu, l, 2);
                float inv = 1.0f / l;
                int qg = qt * 128 + w * 32 + i * 16 + (lane >> 2) + hf * 8;
                bf16* orow = out + (size_t)(b * Tt + qg) * DIMd + h * DHEAD;
#pragma unroll
                for (int j = 0; j < 8; j++) {
                    int d = j * 8 + (lane & 3) * 2;
                    *(unsigned*)(orow + d) =
                        pack_bf2(oAcc[i][j][hf * 2] * inv, oAcc[i][j][hf * 2 + 1] * inv);
                }
            }
        }
    }
}

// ---------------------------------------------------------------------------
// Launch
// Inputs: 0:x 1:action_emb 2:causal_mask 3:Wqkv 4:Wout 5:bout
//         6:W1 7:b1 8:W2 9:b2 10:Wmod 11:bmod
// ---------------------------------------------------------------------------
extern "C" void kernel_launch(void* const* d_in, const int* in_sizes, int n_in,
                              void* d_out, int out_size)
{
    const float* x    = (const float*)d_in[0];
    const float* aemb = (const float*)d_in[1];
    const float* Wqkv = (const float*)d_in[3];
    const float* Wout = (const float*)d_in[4];
    const float* bout = (const float*)d_in[5];
    const float* W1   = (const float*)d_in[6];
    const float* b1   = (const float*)d_in[7];
    const float* W2   = (const float*)d_in[8];
    const float* b2   = (const float*)d_in[9];
    const float* Wmod = (const float*)d_in[10];
    const float* bmod = (const float*)d_in[11];
    float* out = (float*)d_out;

    float *x1_p;
    bf16 *mod_p, *silu_p, *h_p, *qkv_p, *attn_p, *mlp_p;
    bf16 *wqkv_p, *wout_p, *w1_p, *w2_p, *wmod_p;
    cudaGetSymbolAddress((void**)&x1_p,   g_x1);
    cudaGetSymbolAddress((void**)&mod_p,  g_mod_bf);
    cudaGetSymbolAddress((void**)&silu_p, g_silu_bf);
    cudaGetSymbolAddress((void**)&h_p,    g_h_bf);
    cudaGetSymbolAddress((void**)&qkv_p,  g_qkv_bf);
    cudaGetSymbolAddress((void**)&attn_p, g_attn_bf);
    cudaGetSymbolAddress((void**)&mlp_p,  g_mlp_bf);
    cudaGetSymbolAddress((void**)&wqkv_p, g_Wqkv_bf);
    cudaGetSymbolAddress((void**)&wout_p, g_Wout_bf);
    cudaGetSymbolAddress((void**)&w1_p,   g_W1_bf);
    cudaGetSymbolAddress((void**)&w2_p,   g_W2_bf);
    cudaGetSymbolAddress((void**)&wmod_p, g_Wmod_bf);

    cudaFuncSetAttribute(mma_gemm<1>, cudaFuncAttributeMaxDynamicSharedMemorySize, GEMM_SMEM);
    cudaFuncSetAttribute(mma_gemm<2>, cudaFuncAttributeMaxDynamicSharedMemorySize, GEMM_SMEM);
    cudaFuncSetAttribute(mma_gemm<3>, cudaFuncAttributeMaxDynamicSharedMemorySize, GEMM_SMEM);
    cudaFuncSetAttribute(attn_tc_kernel, cudaFuncAttributeMaxDynamicSharedMemorySize, ATTN_SMEM);

    // 1) fused prologue
    prep_kernel<<<(P_S5 + 255) / 256, 256>>>(
        aemb, Wqkv, Wout, W1, W2, Wmod,
        silu_p, wqkv_p, wout_p, w1_p, w2_p, wmod_p);

    // 2) mod = silu_a @ Wmod^T + bmod -> bf16
    mma_gemm<3><<<dim3(MODC / GBN, NTOK / GBM), 256, GEMM_SMEM>>>(
        silu_p, wmod_p, bmod, nullptr, nullptr, 0, mod_p, NTOK, MODC, ADIM);

    // 3) h = LN(x)*(1+scale1)+shift1 -> bf16
    lnmod_kernel<<<NTOK, 128>>>(x, mod_p, 0, DIMd, h_p);

    // 4) qkv = h @ Wqkv^T -> bf16
    mma_gemm<3><<<dim3(QKVC / GBN, NTOK / GBM), 256, GEMM_SMEM>>>(
        h_p, wqkv_p, nullptr, nullptr, nullptr, 0, qkv_p, NTOK, QKVC, DIMd);

    // 5) tensor-core causal attention (diagonal-paired) -> bf16
    attn_tc_kernel<<<dim3(NQT / 2, NHEAD, Bb), 128, ATTN_SMEM>>>(qkv_p, attn_p);

    // 6) x1 = x + gate1 * (attn @ Wout^T + bout)  fp32 out
    mma_gemm<2><<<dim3(DIMd / GBN, NTOK / GBM), 256, GEMM_SMEM>>>(
        attn_p, wout_p, bout, x, mod_p, 2 * DIMd, x1_p, NTOK, DIMd, DIMd);

    // 7) h = LN(x1)*(1+scale2)+shift2 -> bf16
    lnmod_kernel<<<NTOK, 128>>>(x1_p, mod_p, 3 * DIMd, 4 * DIMd, h_p);

    // 8) mlp = gelu(h @ W1^T + b1) -> bf16
    mma_gemm<1><<<dim3(MLPD / GBN, NTOK / GBM), 256, GEMM_SMEM>>>(
        h_p, w1_p, b1, nullptr, nullptr, 0, mlp_p, NTOK, MLPD, DIMd);

    // 9) out = x1 + gate2 * (mlp @ W2^T + b2)  fp32 out
    mma_gemm<2><<<dim3(DIMd / GBN, NTOK / GBM), 256, GEMM_SMEM>>>(
        mlp_p, w2_p, b2, x1_p, mod_p, 5 * DIMd, out, NTOK, DIMd, MLPD);
}